// round 16
// baseline (speedup 1.0000x reference)
#include <cuda_runtime.h>
#include <cstdint>

#define B_  32
#define S_  2048
#define C_  1024
#define G_  16
#define K_  256

// Per-batch block group: 256 producers + 16 selects + 32 copiers = 304.
#define GPROD 256
#define GSEL  16
#define GCOPY 32
#define GRP   (GPROD + GSEL + GCOPY)

__device__ float g_norms[B_ * G_ * S_];                       // (B*g, S)
__device__ __align__(16) unsigned short g_sel[B_ * G_ * K_];  // exact-K lists
__device__ int g_done[B_ * GPROD];                            // producer flags
__device__ int g_flag[B_ * G_];                               // row-ready flags

// ---------------------------------------------------------------------------
// K0: replay-safe flag reset. Flags MUST be re-armed every launch, otherwise
// on graph replay consumers skip their waits and race with the producers'
// zero-fill (the R15 failure). 8704 ints = 34KB; 32 blocks, ~launch latency.
// ---------------------------------------------------------------------------
__global__ __launch_bounds__(256) void k_reset() {
    const int i = blockIdx.x * 256 + threadIdx.x;           // 0..8191
    g_done[i] = 0;
    if (i < B_ * G_) g_flag[i] = 0;
}

// ---------------------------------------------------------------------------
// K1: ONE kernel, batch-interleaved roles. batch = bid/304, within = bid%304:
//   within <256:         PRODUCER — norms + zero-fill for 8 bs-rows; set done.
//   within in [256,272):  SELECT row = batch*16+(within-256). Wait for the
//                        batch's 256 producer flags, radix-select, publish
//                        exact-K list, set g_flag[row].
//   within in [272,304):  COPY — 2 blocks/row, 128 chunks each; wait on
//                        g_flag[row], gather-copy (x + out lines hot in L2).
// All waits target strictly lower block ids -> deadlock-free under in-order
// dispatch. Flags are re-armed by k_reset each launch -> replay-safe.
// ---------------------------------------------------------------------------
__global__ __launch_bounds__(256) void k_all(const float* __restrict__ x,
                                             float* __restrict__ out) {
    const int tid    = threadIdx.x;
    const int batch  = blockIdx.x / GRP;
    const int within = blockIdx.x - batch * GRP;

    if (within < GPROD) {
        // ===================== PRODUCER =====================
        const int base_bs = batch * S_ + within * 8;
        float4 v[8];
        #pragma unroll
        for (int r = 0; r < 8; r++)
            v[r] = reinterpret_cast<const float4*>(
                       x + (size_t)(base_bs + r) * C_)[tid];

        const float4 z = make_float4(0.f, 0.f, 0.f, 0.f);
        #pragma unroll
        for (int r = 0; r < 8; r++)
            reinterpret_cast<float4*>(
                out + (size_t)(base_bs + r) * C_)[tid] = z;

        const int s0 = within * 8;
        #pragma unroll
        for (int r = 0; r < 8; r++) {
            float ss = v[r].x * v[r].x + v[r].y * v[r].y
                     + v[r].z * v[r].z + v[r].w * v[r].w;
            #pragma unroll
            for (int off = 8; off > 0; off >>= 1)
                ss += __shfl_down_sync(0xffffffffu, ss, off, 16);
            if ((tid & 15) == 0)
                g_norms[((batch << 4) + (tid >> 4)) * S_ + (s0 + r)] = ss;
        }
        __syncthreads();
        if (tid == 0) {
            __threadfence();
            atomicExch(&g_done[batch * GPROD + within], 1);
        }

    } else if (within < GPROD + GSEL) {
        // ===================== SELECT =====================
        __shared__ int hist[2][8][256];
        __shared__ int sh_k;
        __shared__ unsigned int sh_prefix;
        __shared__ int wsum[8];
        __shared__ int sh_ngt;
        __shared__ __align__(16) unsigned short sel[K_];

        const int row = batch * G_ + (within - GPROD);   // b*16 + g
        const int w   = tid >> 5;
        const int ln  = tid & 31;

        {
            volatile int* vf = g_done + batch * GPROD + tid;
            while (*vf == 0) __nanosleep(128);
        }
        __syncthreads();
        __threadfence();

        const uint4 a0 = __ldcg(reinterpret_cast<const uint4*>(
                              g_norms + (size_t)row * S_) + tid * 2);
        const uint4 a1 = __ldcg(reinterpret_cast<const uint4*>(
                              g_norms + (size_t)row * S_) + tid * 2 + 1);
        unsigned int u[8] = {a0.x, a0.y, a0.z, a0.w, a1.x, a1.y, a1.z, a1.w};

        if (tid == 0) { sh_k = K_; sh_prefix = 0u; }
        #pragma unroll
        for (int c = 0; c < 8; c++) hist[0][c][tid] = 0;
        __syncthreads();

        int k = K_;
        unsigned int prefix = 0u;
        int cur = 0;
        #pragma unroll
        for (int shift = 24; shift >= 0; shift -= 8) {
            #pragma unroll
            for (int c = 0; c < 8; c++) hist[cur ^ 1][c][tid] = 0;

            if (shift == 24) {
                #pragma unroll
                for (int j = 0; j < 8; j++)
                    atomicAdd(&hist[cur][w][u[j] >> 24], 1);
            } else {
                const unsigned int pmask = 0xFFFFFFFFu << (shift + 8);
                #pragma unroll
                for (int j = 0; j < 8; j++)
                    if ((u[j] & pmask) == prefix)
                        atomicAdd(&hist[cur][w][(u[j] >> shift) & 255], 1);
            }
            __syncthreads();

            if (tid < 32) {
                const int binbase = 255 - tid * 8;
                int bc[8];
                int c = 0;
                #pragma unroll
                for (int j = 0; j < 8; j++) {
                    int h = 0;
                    #pragma unroll
                    for (int cp = 0; cp < 8; cp++)
                        h += hist[cur][cp][binbase - j];
                    bc[j] = h;
                    c += h;
                }
                int inc = c;
                #pragma unroll
                for (int off = 1; off < 32; off <<= 1) {
                    const int nth = __shfl_up_sync(0xffffffffu, inc, off);
                    if (tid >= off) inc += nth;
                }
                const int pre = inc - c;
                const bool hit = (pre < k) && (pre + c >= k);
                const unsigned int bal = __ballot_sync(0xffffffffu, hit);
                if (tid == (__ffs(bal) - 1)) {
                    int cum = pre;
                    #pragma unroll
                    for (int j = 0; j < 8; j++) {
                        if (cum + bc[j] >= k) {
                            sh_k = k - cum;
                            sh_prefix = prefix |
                                ((unsigned int)(binbase - j) << shift);
                            break;
                        }
                        cum += bc[j];
                    }
                }
            }
            __syncthreads();
            k = sh_k;
            prefix = sh_prefix;
            cur ^= 1;
        }

        const float thr = __uint_as_float(prefix);

        // Deterministic exact-K compaction (index-ascending, ties in order).
        int c1 = 0, c2 = 0;
        float fv[8];
        #pragma unroll
        for (int j = 0; j < 8; j++) {
            fv[j] = __uint_as_float(u[j]);
            c1 += (fv[j] > thr) ? 1 : 0;
            c2 += (fv[j] == thr) ? 1 : 0;
        }
        int pk = (c1 << 12) | c2;
        int inc = pk;
        #pragma unroll
        for (int off = 1; off < 32; off <<= 1) {
            const int nth = __shfl_up_sync(0xffffffffu, inc, off);
            if (ln >= off) inc += nth;
        }
        if (ln == 31) wsum[w] = inc;
        __syncthreads();
        if (tid < 8) {
            int v8 = wsum[tid];
            int i8 = v8;
            #pragma unroll
            for (int off = 1; off < 8; off <<= 1) {
                const int nth = __shfl_up_sync(0x000000FFu, i8, off);
                if (tid >= off) i8 += nth;
            }
            wsum[tid] = i8 - v8;
            if (tid == 7) sh_ngt = (i8 >> 12);
        }
        __syncthreads();
        const int ex  = inc - pk + wsum[w];
        const int ngt = sh_ngt;
        const int needed = K_ - ngt;
        int r1 = (ex >> 12) & 0xFFF;
        int r2 = ex & 0xFFF;
        #pragma unroll
        for (int j = 0; j < 8; j++) {
            const int i = tid * 8 + j;
            if (fv[j] > thr) {
                sel[r1++] = (unsigned short)i;
            } else if (fv[j] == thr) {
                if (r2 < needed) sel[ngt + r2] = (unsigned short)i;
                r2++;
            }
        }
        __syncthreads();

        if (tid < 32)
            reinterpret_cast<uint4*>(g_sel + (size_t)row * K_)[tid] =
                reinterpret_cast<const uint4*>(sel)[tid];
        __threadfence();
        __syncthreads();
        if (tid == 0) atomicExch(&g_flag[row], 1);

    } else {
        // ===================== COPY =====================
        const int c    = within - GPROD - GSEL;   // 0..31
        const int row  = batch * G_ + (c >> 1);   // b*16+g
        const int base = (c & 1) * 128;           // half of the 256 chunks
        const int g    = row & 15;
        const int sub  = tid >> 4;   // 0..15
        const int lane = tid & 15;   // 0..15

        if (tid == 0) {
            volatile int* vf = g_flag + row;
            while (*vf == 0) __nanosleep(128);
        }
        __syncthreads();
        __threadfence();

        const unsigned short* srow = g_sel + (size_t)row * K_;
        const float* xb = x   + (size_t)batch * S_ * C_ + g * 64;
        float*       ob = out + (size_t)batch * S_ * C_ + g * 64;

        int si[8];
        #pragma unroll
        for (int it = 0; it < 8; it++)
            si[it] = __ldcg(srow + base + it * 16 + sub);

        float4 v[8];
        #pragma unroll
        for (int it = 0; it < 8; it++)
            v[it] = reinterpret_cast<const float4*>(
                        xb + (size_t)si[it] * C_)[lane];
        #pragma unroll
        for (int it = 0; it < 8; it++)
            reinterpret_cast<float4*>(
                ob + (size_t)si[it] * C_)[lane] = v[it];
    }
}

extern "C" void kernel_launch(void* const* d_in, const int* in_sizes, int n_in,
                              void* d_out, int out_size) {
    const float* x = (const float*)d_in[0];
    float* out = (float*)d_out;
    k_reset<<<B_ * GPROD / 256, 256>>>();
    k_all  <<<B_ * GRP, 256>>>(x, out);
}

// round 17
// speedup vs baseline: 1.0313x; 1.0313x over previous
#include <cuda_runtime.h>
#include <cstdint>

#define B_  32
#define S_  2048
#define C_  1024
#define G_  16
#define K_  256

#define NPROD (B_ * S_ / 8)   // 8192 producer blocks
#define NTAIL (B_ * G_)       // 512 fused select+copy blocks

__device__ float g_norms[B_ * G_ * S_];   // (B*g, S)
__device__ int   g_cnt  [B_ * G_];        // per-row producer counters
                                          // (zero-init; consumers re-arm)

// ---------------------------------------------------------------------------
// ONE kernel, one launch. blockIdx.x:
//  [0, 8192):     PRODUCER — norms + zero-fill for 8 bs-rows (proven shape),
//                 fence, then tid<16 increment the batch's 16 row counters.
//  [8192, 8704):  TAIL (fused select+copy) for row = bid-8192. tid0 spins
//                 until g_cnt[row]==256, RESETS it to 0 (re-arms the wait for
//                 the next graph replay -> replay-safe), then the block does
//                 the register-resident 4-pass radix select, deterministic
//                 exact-K compaction in smem, and copies all 256 selected
//                 64-channel chunks (zeros were pre-written by producers and
//                 are ordered before the counter increment).
// Waits target strictly lower block ids -> deadlock-free in-order dispatch.
// ---------------------------------------------------------------------------
__global__ __launch_bounds__(256) void k_all(const float* __restrict__ x,
                                             float* __restrict__ out) {
    const int tid = threadIdx.x;
    const int bid = blockIdx.x;

    if (bid < NPROD) {
        // ===================== PRODUCER =====================
        const int base_bs = bid << 3;
        const int batch   = bid >> 8;          // 256 producer blocks per batch
        float4 v[8];
        #pragma unroll
        for (int r = 0; r < 8; r++)
            v[r] = reinterpret_cast<const float4*>(
                       x + (size_t)(base_bs + r) * C_)[tid];

        const float4 z = make_float4(0.f, 0.f, 0.f, 0.f);
        #pragma unroll
        for (int r = 0; r < 8; r++)
            __stcs(reinterpret_cast<float4*>(
                       out + (size_t)(base_bs + r) * C_) + tid, z);

        const int s0 = base_bs & (S_ - 1);
        #pragma unroll
        for (int r = 0; r < 8; r++) {
            float ss = v[r].x * v[r].x + v[r].y * v[r].y
                     + v[r].z * v[r].z + v[r].w * v[r].w;
            #pragma unroll
            for (int off = 8; off > 0; off >>= 1)
                ss += __shfl_down_sync(0xffffffffu, ss, off, 16);
            if ((tid & 15) == 0)
                g_norms[((batch << 4) + (tid >> 4)) * S_ + (s0 + r)] = ss;
        }
        __syncthreads();
        __threadfence();
        if (tid < G_)
            atomicAdd(&g_cnt[(batch << 4) + tid], 1);

    } else {
        // ===================== TAIL: fused select + copy =====================
        __shared__ int hist[2][8][256];
        __shared__ int sh_k;
        __shared__ unsigned int sh_prefix;
        __shared__ int wsum[8];
        __shared__ int sh_ngt;
        __shared__ unsigned short sel[K_];

        const int row = bid - NPROD;           // b*16 + g
        const int b   = row >> 4;
        const int g   = row & 15;
        const int w   = tid >> 5;
        const int ln  = tid & 31;

        // Wait for all 256 producers of this batch (counter == 256), then
        // re-arm for the next replay.
        if (tid == 0) {
            volatile int* vc = g_cnt + row;
            while (*vc != 256) __nanosleep(128);
            *vc = 0;                            // re-arm (replay safety)
        }
        __syncthreads();
        __threadfence();

        const uint4 a0 = __ldcg(reinterpret_cast<const uint4*>(
                              g_norms + (size_t)row * S_) + tid * 2);
        const uint4 a1 = __ldcg(reinterpret_cast<const uint4*>(
                              g_norms + (size_t)row * S_) + tid * 2 + 1);
        unsigned int u[8] = {a0.x, a0.y, a0.z, a0.w, a1.x, a1.y, a1.z, a1.w};

        if (tid == 0) { sh_k = K_; sh_prefix = 0u; }
        #pragma unroll
        for (int c = 0; c < 8; c++) hist[0][c][tid] = 0;
        __syncthreads();

        int k = K_;
        unsigned int prefix = 0u;
        int cur = 0;
        #pragma unroll
        for (int shift = 24; shift >= 0; shift -= 8) {
            #pragma unroll
            for (int c = 0; c < 8; c++) hist[cur ^ 1][c][tid] = 0;

            if (shift == 24) {
                #pragma unroll
                for (int j = 0; j < 8; j++)
                    atomicAdd(&hist[cur][w][u[j] >> 24], 1);
            } else {
                const unsigned int pmask = 0xFFFFFFFFu << (shift + 8);
                #pragma unroll
                for (int j = 0; j < 8; j++)
                    if ((u[j] & pmask) == prefix)
                        atomicAdd(&hist[cur][w][(u[j] >> shift) & 255], 1);
            }
            __syncthreads();

            if (tid < 32) {
                const int binbase = 255 - tid * 8;
                int bc[8];
                int c = 0;
                #pragma unroll
                for (int j = 0; j < 8; j++) {
                    int h = 0;
                    #pragma unroll
                    for (int cp = 0; cp < 8; cp++)
                        h += hist[cur][cp][binbase - j];
                    bc[j] = h;
                    c += h;
                }
                int inc = c;
                #pragma unroll
                for (int off = 1; off < 32; off <<= 1) {
                    const int nth = __shfl_up_sync(0xffffffffu, inc, off);
                    if (tid >= off) inc += nth;
                }
                const int pre = inc - c;
                const bool hit = (pre < k) && (pre + c >= k);
                const unsigned int bal = __ballot_sync(0xffffffffu, hit);
                if (tid == (__ffs(bal) - 1)) {
                    int cum = pre;
                    #pragma unroll
                    for (int j = 0; j < 8; j++) {
                        if (cum + bc[j] >= k) {
                            sh_k = k - cum;
                            sh_prefix = prefix |
                                ((unsigned int)(binbase - j) << shift);
                            break;
                        }
                        cum += bc[j];
                    }
                }
            }
            __syncthreads();
            k = sh_k;
            prefix = sh_prefix;
            cur ^= 1;
        }

        const float thr = __uint_as_float(prefix);

        // Deterministic exact-K compaction (index-ascending, ties in order).
        int c1 = 0, c2 = 0;
        float fv[8];
        #pragma unroll
        for (int j = 0; j < 8; j++) {
            fv[j] = __uint_as_float(u[j]);
            c1 += (fv[j] > thr) ? 1 : 0;
            c2 += (fv[j] == thr) ? 1 : 0;
        }
        int pk = (c1 << 12) | c2;
        int inc = pk;
        #pragma unroll
        for (int off = 1; off < 32; off <<= 1) {
            const int nth = __shfl_up_sync(0xffffffffu, inc, off);
            if (ln >= off) inc += nth;
        }
        if (ln == 31) wsum[w] = inc;
        __syncthreads();
        if (tid < 8) {
            int v8 = wsum[tid];
            int i8 = v8;
            #pragma unroll
            for (int off = 1; off < 8; off <<= 1) {
                const int nth = __shfl_up_sync(0x000000FFu, i8, off);
                if (tid >= off) i8 += nth;
            }
            wsum[tid] = i8 - v8;
            if (tid == 7) sh_ngt = (i8 >> 12);
        }
        __syncthreads();
        const int ex  = inc - pk + wsum[w];
        const int ngt = sh_ngt;
        const int needed = K_ - ngt;
        int r1 = (ex >> 12) & 0xFFF;
        int r2 = ex & 0xFFF;
        #pragma unroll
        for (int j = 0; j < 8; j++) {
            const int i = tid * 8 + j;
            if (fv[j] > thr) {
                sel[r1++] = (unsigned short)i;
            } else if (fv[j] == thr) {
                if (r2 < needed) sel[ngt + r2] = (unsigned short)i;
                r2++;
            }
        }
        __syncthreads();

        // Copy all 256 selected chunks (R11-proven: 16 subs x 16 lanes,
        // front-batched 8-deep, two halves).
        const int sub  = tid >> 4;
        const int lane = tid & 15;
        const float* xb = x   + (size_t)b * S_ * C_ + g * 64;
        float*       ob = out + (size_t)b * S_ * C_ + g * 64;

        #pragma unroll
        for (int half = 0; half < 2; half++) {
            int si[8];
            float4 v[8];
            #pragma unroll
            for (int it = 0; it < 8; it++)
                si[it] = sel[(half * 8 + it) * 16 + sub];
            #pragma unroll
            for (int it = 0; it < 8; it++)
                v[it] = reinterpret_cast<const float4*>(
                            xb + (size_t)si[it] * C_)[lane];
            #pragma unroll
            for (int it = 0; it < 8; it++)
                __stcs(reinterpret_cast<float4*>(
                           ob + (size_t)si[it] * C_) + lane, v[it]);
        }
    }
}

extern "C" void kernel_launch(void* const* d_in, const int* in_sizes, int n_in,
                              void* d_out, int out_size) {
    const float* x = (const float*)d_in[0];
    float* out = (float*)d_out;
    k_all<<<NPROD + NTAIL, 256>>>(x, out);
}